// round 7
// baseline (speedup 1.0000x reference)
#include <cuda_runtime.h>
#include <math.h>

#define L_ 520
#define V_ 32128
#define R_ 512
#define KK 8                         // K = L - R
#define V4 (V_ / 4)                  // 8032
#define OUT_PROBS_OFF 521
#define TOTAL_ELEMS ((size_t)L_ * V_)                  // 16706560
#define OUT_NMATCH (OUT_PROBS_OFF + TOTAL_ELEMS)       // 16707081
#define ROW512_BASE (OUT_PROBS_OFF + (size_t)R_ * V_)  // 16450057
#define ELEM_STRADDLE (ROW512_BASE - 1)                // 16450056 = probs[512*V-1]
// dst float4 q covers out[4q..4q+3]; src elem f = 4q-521
#define Q_FIRST 131
#define QC_LAST 4112513              // last dst float4 fully inside rows < 512
#define ROW_BLOCKS 9
#define COPY_BLOCKS 1004
#define COPY_STRIDE (COPY_BLOCKS * 1024)
#define GRID1 (ROW_BLOCKS + COPY_BLOCKS)
#define ZTOTAL (KK * V_)             // 257024 elems in the maskable region

struct Scratch {
    float rmax[ROW_BLOCKS];
    float rsuminv[ROW_BLOCKS];
    int   rargmax[ROW_BLOCKS];
};
__device__ Scratch g_s;              // fully overwritten by launch 1 every run

// ---------------------------------------------------------------------------
// Launch 1. Blocks 0..8: one full logits row each (row 511+i). Self-contained:
// max/argmax pass, then (i<8) unnormalized exp written to out row 512+i with
// sum accumulation, then rescale by 1/sum. Blocks 9..1012: aligned bulk copy
// of the rows<512 output region (shuffle realignment, 4 float4 tasks/thread).
// No atomics, no inter-block dependencies of any kind.
// ---------------------------------------------------------------------------
__global__ void __launch_bounds__(1024) fused1_kernel(
        const float* __restrict__ logits,
        const float* __restrict__ probs,
        float* __restrict__ out) {
    const int tid = threadIdx.x;
    const int bid = blockIdx.x;

    if (bid >= ROW_BLOCKS) {
        // ---------------- copy path ----------------
        const int t = (bid - ROW_BLOCKS) * 1024 + tid;
        const int lane = tid & 31;
        const float4* __restrict__ probs4 = (const float4*)probs;

        int q[4]; bool act[4]; float4 A[4];
        #pragma unroll
        for (int k = 0; k < 4; k++) {
            q[k] = Q_FIRST + k * COPY_STRIDE + t;
            act[k] = (q[k] <= QC_LAST);
        }
        #pragma unroll
        for (int k = 0; k < 4; k++)
            if (act[k]) A[k] = __ldcs(probs4 + (q[k] - 130));
        float pw[4];
        #pragma unroll
        for (int k = 0; k < 4; k++) {
            pw[k] = __shfl_up_sync(0xffffffffu, A[k].w, 1);
            if (lane == 0 && act[k])
                pw[k] = __ldcs(probs + (size_t)4 * q[k] - 521);
        }
        #pragma unroll
        for (int k = 0; k < 4; k++) {
            if (act[k]) {
                float4 o; o.x = pw[k]; o.y = A[k].x; o.z = A[k].y; o.w = A[k].z;
                __stcs(((float4*)out) + q[k], o);
            }
        }
        return;
    }

    // ---------------- row path: one block = one full row ----------------
    const int i = bid;                                  // 0..8 -> logits row 511+i
    const float4* __restrict__ row4 =
        (const float4*)(logits + (size_t)(R_ - 1 + i) * V_);

    __shared__ float srm[1024];
    __shared__ int   sra[1024];

    // pass 1: max + first-index argmax
    float m = -INFINITY; int am = 0x7fffffff;
    for (int j = tid; j < V4; j += 1024) {
        float4 v = row4[j];
        int cb = 4 * j;
        if (v.x > m) { m = v.x; am = cb; }
        if (v.y > m) { m = v.y; am = cb + 1; }
        if (v.z > m) { m = v.z; am = cb + 2; }
        if (v.w > m) { m = v.w; am = cb + 3; }
    }
    srm[tid] = m; sra[tid] = am;
    __syncthreads();
    for (int off = 512; off > 0; off >>= 1) {
        if (tid < off) {
            float mv = srm[tid + off]; int mi = sra[tid + off];
            if (mv > srm[tid] || (mv == srm[tid] && mi < sra[tid])) {
                srm[tid] = mv; sra[tid] = mi;
            }
        }
        __syncthreads();
    }
    const float rowmax = srm[0];
    const int   rowarg = sra[0];
    __syncthreads();

    if (i == KK) {                    // row 519: only argmax needed
        if (tid == 0) {
            g_s.rmax[KK] = rowmax; g_s.rsuminv[KK] = 0.f; g_s.rargmax[KK] = rowarg;
        }
        return;
    }

    // pass 2: unnormalized exp -> out row 512+i, accumulate sum (L1/L2 hot)
    float* obase = out + ROW512_BASE + (size_t)i * V_;
    float acc = 0.f;
    for (int j = tid; j < V4; j += 1024) {
        float4 v = row4[j];
        float e0 = expf(v.x - rowmax), e1 = expf(v.y - rowmax);
        float e2 = expf(v.z - rowmax), e3 = expf(v.w - rowmax);
        acc += (e0 + e1) + (e2 + e3);
        int cb = 4 * j;
        obase[cb] = e0; obase[cb + 1] = e1; obase[cb + 2] = e2; obase[cb + 3] = e3;
    }
    srm[tid] = acc;
    __syncthreads();
    for (int off = 512; off > 0; off >>= 1) {
        if (tid < off) srm[tid] += srm[tid + off];
        __syncthreads();
    }
    const float si = 1.0f / srm[0];
    if (tid == 0) {
        g_s.rmax[i] = rowmax; g_s.rsuminv[i] = si; g_s.rargmax[i] = rowarg;
    }

    // pass 3: rescale own elements (each thread re-reads only its own stores)
    for (int j = tid; j < V4; j += 1024) {
        int cb = 4 * j;
        obase[cb]     *= si; obase[cb + 1] *= si;
        obase[cb + 2] *= si; obase[cb + 3] *= si;
    }
}

// ---------------------------------------------------------------------------
// Launch 2. Every block independently recomputes n_match from g_s (written by
// launch 1; ordered by the stream) + 16 gathers -> identical result in every
// block, no communication. Block 0: ids + scalars + straddle element.
// Blocks 1..256: zero out rows >= n_match (write-only).
// ---------------------------------------------------------------------------
__global__ void __launch_bounds__(256) finish2_kernel(
        const float* __restrict__ logits,
        const float* __restrict__ probs,
        const void*  __restrict__ ids_raw,
        float* __restrict__ out) {
    const int tid = threadIdx.x;
    const int bid = blockIdx.x;

    // int64-vs-int32 detection (all odd 32-bit words zero => int64 layout)
    const int* w = (const int*)ids_raw;
    int flag = 0;
    for (int j = 1 + 2 * tid; j < L_; j += 2 * 256)
        if (w[j] != 0) flag = 1;
    const int any = __syncthreads_or(flag);
    const int is64 = (any == 0);
    const long long* w64 = (const long long*)ids_raw;

    __shared__ int s_nm;
    if (tid == 0) {
        int d[KK]; float tl[KK], pp[KK];
        #pragma unroll
        for (int k = 0; k < KK; k++)
            d[k] = is64 ? (int)w64[R_ + k] : w[R_ + k];
        #pragma unroll
        for (int k = 0; k < KK; k++) {
            tl[k] = __ldg(&logits[(size_t)(R_ - 1 + k) * V_ + d[k]]);
            pp[k] = __ldg(&probs [(size_t)(R_ - 1 + k) * V_ + d[k]]);
        }
        int nm = 0; bool chain = true;
        #pragma unroll
        for (int k = 0; k < KK; k++) {
            float tp = expf(tl[k] - g_s.rmax[k]) * g_s.rsuminv[k];
            bool acc = (g_s.rargmax[k] == d[k]) || (tp > pp[k] * 0.5f); // leniency=2
            if (chain && acc) nm++; else chain = false;
        }
        s_nm = nm;
    }
    __syncthreads();
    const int nm = s_nm;

    if (bid == 0) {
        if (tid == 0) {
            out[OUT_NMATCH] = (float)nm;
            out[OUT_PROBS_OFF + 0] = probs[0];
            out[OUT_PROBS_OFF + 1] = probs[1];
            out[OUT_PROBS_OFF + 2] = probs[2];
            out[ELEM_STRADDLE] = probs[(size_t)R_ * V_ - 1];
        }
        // id_res[0:512]
        for (int j = tid; j < R_; j += 256)
            out[j] = (float)(is64 ? (int)w64[j] : w[j]);
        // id_res[512:521]
        if (tid <= KK) {
            int pos = tid, v;
            if      (pos < nm)  v = is64 ? (int)w64[R_ + pos] : w[R_ + pos];
            else if (pos == nm) v = g_s.rargmax[pos];
            else                v = 0;
            out[R_ + pos] = (float)v;
        }
        return;
    }

    // zeroing blocks: region elems e in [0, 8*V), out index ROW512_BASE + e
    const int ebase = ((bid - 1) * 256 + tid) * 4;
    #pragma unroll
    for (int c = 0; c < 4; c++) {
        int e = ebase + c;
        if (e < ZTOTAL) {
            int j = (unsigned)e / (unsigned)V_;   // row 0..7 (magic-mul)
            if (j >= nm) out[ROW512_BASE + e] = 0.f;
        }
    }
}

// ---------------------------------------------------------------------------
extern "C" void kernel_launch(void* const* d_in, const int* in_sizes, int n_in,
                              void* d_out, int out_size) {
    const float* logits = (const float*)d_in[0];
    const float* probs  = (const float*)d_in[1];
    const void*  ids    = d_in[2];
    float* out = (float*)d_out;

    fused1_kernel<<<GRID1, 1024>>>(logits, probs, out);
    finish2_kernel<<<1 + 256, 256>>>(logits, probs, ids, out);
}